// round 1
// baseline (speedup 1.0000x reference)
#include <cuda_runtime.h>
#include <math.h>

// Problem constants (fixed shapes for HoughSplitLoss_12884901888574)
#define B_   32
#define L_   6
#define A_   1024
#define R_   1024
#define NPTS (B_ * L_)            // 192
#define RAD  5
#define WIN  11                   // 2*RAD+1
#define NWIN (WIN * WIN)          // 121
#define NELEM (1024u * 1024u)     // per-batch plane elements
#define TOTAL_ELEMS ((long long)B_ * A_ * R_)  // 33554432

// Scratch state (no device allocation allowed; rewritten deterministically
// every launch by loss_main, so graph replays are self-consistent).
__device__ int    g_flag;       // 1 => main path wrote d_out; 0 => fallback needed
__device__ double g_fallback;   // fallback accumulator (zeroed when flag==0)

__device__ __forceinline__ float sigmoidf_(float x) {
    return 1.0f / (1.0f + expf(-x));
}

// ---------------------------------------------------------------------------
// Kernel 1: the entire main loss path in ONE block (deterministic reduction).
// 512 threads = 16 warps; warp w handles points p = w, w+16, ... (12 each).
// ---------------------------------------------------------------------------
__global__ __launch_bounds__(512)
void loss_main(const float* __restrict__ pre_hough,
               const float* __restrict__ gt_hough,
               const int*   __restrict__ in_pre_points,
               const int*   __restrict__ gt_points,
               float*       __restrict__ out)
{
    __shared__ int   s_x[NPTS];
    __shared__ int   s_y[NPTS];
    __shared__ float s_w[NPTS];
    __shared__ float s_warp[16];

    const int tid = threadIdx.x;

    // ---- Phase 0: per-batch point prep (thread b handles batch b) ----
    if (tid < B_) {
        const int b = tid;
        int       px[L_], py[L_];
        long long key[L_];
        #pragma unroll
        for (int l = 0; l < L_; ++l) {
            px[l] = in_pre_points[(b * L_ + l) * 2 + 0];
            py[l] = in_pre_points[(b * L_ + l) * 2 + 1];
            key[l] = (px[l] < 0) ? (1LL << 30)
                                 : (long long)px[l] * 10000LL + (long long)py[l];
        }
        // Stable insertion sort by key (matches stable argsort semantics;
        // ties are outcome-neutral anyway).
        #pragma unroll
        for (int i = 1; i < L_; ++i) {
            long long kk = key[i];
            int kx = px[i], ky = py[i];
            int j = i - 1;
            while (j >= 0 && key[j] > kk) {
                key[j + 1] = key[j];
                px[j + 1]  = px[j];
                py[j + 1]  = py[j];
                --j;
            }
            key[j + 1] = kk; px[j + 1] = kx; py[j + 1] = ky;
        }
        #pragma unroll
        for (int l = 0; l < L_; ++l) {
            const int gx = gt_points[(b * L_ + l) * 2 + 0];
            const int gy = gt_points[(b * L_ + l) * 2 + 1];
            const bool use_gt = (gx >= 0);
            const int X = use_gt ? gx : px[l];
            const int Y = use_gt ? gy : py[l];
            const bool one_inv  = (px[l] < 0) || (gx < 0);
            const bool both_inv = (px[l] < 0) && (gx < 0);
            const int idx = b * L_ + l;
            s_x[idx] = X;
            s_y[idx] = Y;
            s_w[idx] = both_inv ? 0.0f
                                : (one_inv ? 10.0f : 1.0f) / (float)(RAD * RAD);
        }
    }
    __syncthreads();

    // ---- Phase 1: one warp per point, 11x11 gathered window ----
    const int warp = tid >> 5;
    const int lane = tid & 31;
    float wacc = 0.0f;

    for (int p = warp; p < NPTS; p += 16) {
        const int b = p / L_;
        const float* __restrict__ phb = pre_hough + (size_t)b * NELEM;
        const float* __restrict__ gpb = gt_hough  + (size_t)b * NELEM;
        const int X = s_x[p];
        const int Y = s_y[p];

        float acc = 0.0f;
        #pragma unroll
        for (int it = 0; it < 4; ++it) {
            const int idx = lane + it * 32;
            if (idx < NWIN) {
                const int di = idx / WIN - RAD;
                const int dj = idx % WIN - RAD;
                const int xi = X + di;
                const int yi = Y + dj;
                // mx: 0 <= xi < R ; my: 0 <= yi < A  (both 1024; masked-out
                // elements contribute 0, so skip instead of clip+multiply)
                if (xi >= 0 && xi < R_ && yi >= 0 && yi < A_) {
                    const float v = sigmoidf_(phb[xi * R_ + yi]);
                    acc += fabsf(v - gpb[xi * R_ + yi]);
                }
            }
        }
        // warp reduce (deterministic)
        #pragma unroll
        for (int off = 16; off > 0; off >>= 1)
            acc += __shfl_down_sync(0xffffffffu, acc, off);
        if (lane == 0)
            wacc += acc * s_w[p];
    }

    if (lane == 0) s_warp[warp] = wacc;
    __syncthreads();

    if (tid == 0) {
        float total = 0.0f;
        #pragma unroll
        for (int w = 0; w < 16; ++w) total += s_warp[w];
        if (total != 0.0f) {
            out[0] = total / (float)B_;
            g_flag = 1;
        } else {
            g_flag = 0;
            g_fallback = 0.0;
        }
    }
}

// ---------------------------------------------------------------------------
// Kernel 2: fallback partial sums (mean |sigmoid(pre)-gt|). Early-exits when
// the main path already produced the answer (the overwhelmingly common case:
// cost = one global load per block).
// ---------------------------------------------------------------------------
__global__ __launch_bounds__(256)
void loss_fallback(const float* __restrict__ pre_hough,
                   const float* __restrict__ gt_hough)
{
    if (g_flag) return;

    __shared__ double s_red[256];
    const long long stride = (long long)gridDim.x * blockDim.x;
    long long i = (long long)blockIdx.x * blockDim.x + threadIdx.x;

    double acc = 0.0;
    for (; i < TOTAL_ELEMS; i += stride) {
        const float v = sigmoidf_(pre_hough[i]);
        acc += (double)fabsf(v - gt_hough[i]);
    }
    s_red[threadIdx.x] = acc;
    __syncthreads();
    for (int off = 128; off > 0; off >>= 1) {
        if (threadIdx.x < off) s_red[threadIdx.x] += s_red[threadIdx.x + off];
        __syncthreads();
    }
    if (threadIdx.x == 0)
        atomicAdd(&g_fallback, s_red[0]);
}

__global__ void loss_fallback_finalize(float* __restrict__ out)
{
    if (!g_flag)
        out[0] = (float)(g_fallback / (double)TOTAL_ELEMS);
}

// ---------------------------------------------------------------------------
extern "C" void kernel_launch(void* const* d_in, const int* in_sizes, int n_in,
                              void* d_out, int out_size)
{
    const float* pre_hough     = (const float*)d_in[0];
    const float* gt_hough      = (const float*)d_in[1];
    const int*   in_pre_points = (const int*)d_in[2];
    const int*   gt_points     = (const int*)d_in[3];
    float*       out           = (float*)d_out;

    loss_main<<<1, 512>>>(pre_hough, gt_hough, in_pre_points, gt_points, out);
    loss_fallback<<<256, 256>>>(pre_hough, gt_hough);
    loss_fallback_finalize<<<1, 1>>>(out);
}

// round 2
// speedup vs baseline: 3.1254x; 3.1254x over previous
#include <cuda_runtime.h>
#include <math.h>

// Problem constants (fixed shapes for HoughSplitLoss_12884901888574)
#define B_   32
#define L_   6
#define A_   1024
#define R_   1024
#define NPTS (B_ * L_)            // 192
#define RAD  5
#define WIN  11                   // 2*RAD+1
#define NWIN (WIN * WIN)          // 121
#define NELEM (1024u * 1024u)     // per-batch plane elements
#define TOTAL_ELEMS ((long long)B_ * A_ * R_)  // 33554432

// Fixed-point scales for deterministic integer accumulation.
#define SCALE_MAIN 4194304.0      // 2^22  (total <= ~1e3 -> acc <= ~2^32, fits u64)
#define SCALE_FB   1048576.0      // 2^20  (sum <= ~1.7e7 -> acc <= ~2^44)

// Scratch globals. Zero-initialized at module load; the elected last block of
// each kernel restores them to zero after reading, so every launch (correctness
// run, every graph replay) sees the same initial state -> fully deterministic.
__device__ unsigned long long g_acc;   // main-path fixed-point accumulator
__device__ unsigned int       g_cnt;   // main-path block arrival counter
__device__ int                g_flag;  // 1 => main path wrote d_out
__device__ unsigned long long g_facc;  // fallback accumulator
__device__ unsigned int       g_fcnt;  // fallback arrival counter

__device__ __forceinline__ float sigmoidf_(float x) {
    return 1.0f / (1.0f + expf(-x));
}

// ---------------------------------------------------------------------------
// Kernel 1: one block per (batch, point). 128 threads; thread t owns window
// cell t (121 cells). Block-level float reduce (deterministic), then a
// fixed-point atomicAdd into g_acc (integer atomics are order-independent).
// The last-arriving block finalizes: writes out, sets flag, resets globals.
// ---------------------------------------------------------------------------
__global__ __launch_bounds__(128)
void loss_main(const float* __restrict__ pre_hough,
               const float* __restrict__ gt_hough,
               const int*   __restrict__ in_pre_points,
               const int*   __restrict__ gt_points,
               float*       __restrict__ out)
{
    __shared__ int   sX, sY;
    __shared__ float sW;
    __shared__ float s_part[4];

    const int p = blockIdx.x;       // 0..191
    const int b = p / L_;
    const int l = p - b * L_;
    const int tid = threadIdx.x;

    // ---- Point prep (thread 0): load batch b's 6 pre-points, stable sort,
    //      select point l, compute weight. 3 vector loads, all independent. ----
    if (tid == 0) {
        const int4* pp = (const int4*)(in_pre_points + b * (L_ * 2));
        const int4 v0 = pp[0], v1 = pp[1], v2 = pp[2];
        int px[L_] = { v0.x, v0.z, v1.x, v1.z, v2.x, v2.z };
        int py[L_] = { v0.y, v0.w, v1.y, v1.w, v2.y, v2.w };
        long long key[L_];
        #pragma unroll
        for (int i = 0; i < L_; ++i)
            key[i] = (px[i] < 0) ? (1LL << 30)
                                 : (long long)px[i] * 10000LL + (long long)py[i];
        // Stable insertion sort (matches stable argsort; ties outcome-neutral).
        #pragma unroll
        for (int i = 1; i < L_; ++i) {
            long long kk = key[i];
            int kx = px[i], ky = py[i];
            int j = i - 1;
            while (j >= 0 && key[j] > kk) {
                key[j + 1] = key[j]; px[j + 1] = px[j]; py[j + 1] = py[j];
                --j;
            }
            key[j + 1] = kk; px[j + 1] = kx; py[j + 1] = ky;
        }
        const int2 g = ((const int2*)(gt_points + b * (L_ * 2)))[l];
        const bool use_gt  = (g.x >= 0);
        const bool one_inv  = (px[l] < 0) || (g.x < 0);
        const bool both_inv = (px[l] < 0) && (g.x < 0);
        sX = use_gt ? g.x : px[l];
        sY = use_gt ? g.y : py[l];
        sW = both_inv ? 0.0f : (one_inv ? 10.0f : 1.0f) / (float)(RAD * RAD);
    }
    __syncthreads();

    // ---- Gather: one window cell per thread (121 of 128 active) ----
    float acc = 0.0f;
    if (tid < NWIN) {
        const int di = tid / WIN - RAD;
        const int dj = tid % WIN - RAD;
        const int xi = sX + di;
        const int yi = sY + dj;
        if (xi >= 0 && xi < R_ && yi >= 0 && yi < A_) {
            const size_t off = (size_t)b * NELEM + (size_t)xi * R_ + yi;
            acc = fabsf(sigmoidf_(pre_hough[off]) - gt_hough[off]);
        }
    }

    // ---- Deterministic block reduce: warp shuffle -> 4 partials -> thread 0 ----
    #pragma unroll
    for (int off = 16; off > 0; off >>= 1)
        acc += __shfl_down_sync(0xffffffffu, acc, off);
    if ((tid & 31) == 0) s_part[tid >> 5] = acc;
    __syncthreads();

    if (tid == 0) {
        const float sum = (s_part[0] + s_part[1]) + (s_part[2] + s_part[3]);
        const long long q = __double2ll_rn((double)(sum * sW) * SCALE_MAIN);
        atomicAdd(&g_acc, (unsigned long long)q);
        __threadfence();
        const unsigned old = atomicAdd(&g_cnt, 1u);
        if (old == (unsigned)(gridDim.x - 1)) {
            const unsigned long long a = atomicAdd(&g_acc, 0ULL);
            const float total = (float)((double)a / SCALE_MAIN);
            if (total != 0.0f) {
                out[0] = total / (float)B_;
                g_flag = 1;
            } else {
                g_flag = 0;
            }
            // Restore invariant for next launch/replay.
            g_acc  = 0ULL;
            g_cnt  = 0u;
            g_facc = 0ULL;
            g_fcnt = 0u;
            __threadfence();
        }
    }
}

// ---------------------------------------------------------------------------
// Kernel 2: fallback mean |sigmoid(pre)-gt| over all 33.5M elements.
// Early-exits when the main path produced the answer (the common case:
// cost = one global load per block). Deterministic fixed-point accumulation;
// last block finalizes and resets its own globals.
// ---------------------------------------------------------------------------
__global__ __launch_bounds__(256)
void loss_fallback(const float* __restrict__ pre_hough,
                   const float* __restrict__ gt_hough,
                   float*       __restrict__ out)
{
    if (g_flag) return;

    __shared__ double s_red[256];
    const long long stride = (long long)gridDim.x * blockDim.x;
    long long i = (long long)blockIdx.x * blockDim.x + threadIdx.x;

    double acc = 0.0;
    for (; i < TOTAL_ELEMS; i += stride)
        acc += (double)fabsf(sigmoidf_(pre_hough[i]) - gt_hough[i]);

    s_red[threadIdx.x] = acc;
    __syncthreads();
    for (int off = 128; off > 0; off >>= 1) {
        if (threadIdx.x < off) s_red[threadIdx.x] += s_red[threadIdx.x + off];
        __syncthreads();
    }
    if (threadIdx.x == 0) {
        const long long q = __double2ll_rn(s_red[0] * SCALE_FB);
        atomicAdd(&g_facc, (unsigned long long)q);
        __threadfence();
        const unsigned old = atomicAdd(&g_fcnt, 1u);
        if (old == (unsigned)(gridDim.x - 1)) {
            const unsigned long long a = atomicAdd(&g_facc, 0ULL);
            out[0] = (float)(((double)a / SCALE_FB) / (double)TOTAL_ELEMS);
            g_facc = 0ULL;
            g_fcnt = 0u;
            __threadfence();
        }
    }
}

// ---------------------------------------------------------------------------
extern "C" void kernel_launch(void* const* d_in, const int* in_sizes, int n_in,
                              void* d_out, int out_size)
{
    const float* pre_hough     = (const float*)d_in[0];
    const float* gt_hough      = (const float*)d_in[1];
    const int*   in_pre_points = (const int*)d_in[2];
    const int*   gt_points     = (const int*)d_in[3];
    float*       out           = (float*)d_out;

    loss_main<<<NPTS, 128>>>(pre_hough, gt_hough, in_pre_points, gt_points, out);
    loss_fallback<<<256, 256>>>(pre_hough, gt_hough, out);
}